// round 4
// baseline (speedup 1.0000x reference)
#include <cuda_runtime.h>

// CostVolumeBidirectional: f1,f2 (8,96,96,320) f32 -> out (8,9,96,320) f32
// out[b][d][h][w] = (1/96) * sum_c f1[b][c][h][w] * f2[b][c][h][w-(d-4)]
// zero where w-(d-4) outside [0,320).

#define BS 8
#define FS 96
#define H  96
#define W  320
#define WQ (W / 4)      // 80 float4 groups per row
#define NP 9            // disparity planes

__global__ __launch_bounds__(256, 8)
void cost_volume_kernel(const float* __restrict__ f1,
                        const float* __restrict__ f2,
                        float* __restrict__ out) {
    int t = blockIdx.x * blockDim.x + threadIdx.x;
    if (t >= BS * H * WQ) return;

    int wq = t % WQ;
    int bh = t / WQ;          // b*H + h
    int h  = bh % H;
    int b  = bh / H;

    // accumulators: 9 planes x 4 columns
    float acc[NP][4];
#pragma unroll
    for (int d = 0; d < NP; d++)
#pragma unroll
        for (int k = 0; k < 4; k++) acc[d][k] = 0.0f;

    const int cs = H * W;                               // channel stride
    const size_t base = ((size_t)b * FS) * cs + (size_t)h * W + (size_t)wq * 4;
    const float* p1 = f1 + base;
    const float* p2 = f2 + base;

    const bool hasL = (wq > 0);
    const bool hasR = (wq < WQ - 1);
    const float4 z4 = make_float4(0.f, 0.f, 0.f, 0.f);

#pragma unroll 4
    for (int c = 0; c < FS; c++) {
        const float* q1 = p1 + (size_t)c * cs;
        const float* q2 = p2 + (size_t)c * cs;

        float4 a = *(const float4*)(q1);
        float4 m = *(const float4*)(q2);
        float4 l = hasL ? *(const float4*)(q2 - 4) : z4;
        float4 r = hasR ? *(const float4*)(q2 + 4) : z4;

        float w12[12] = {l.x, l.y, l.z, l.w,
                         m.x, m.y, m.z, m.w,
                         r.x, r.y, r.z, r.w};
        float av[4] = {a.x, a.y, a.z, a.w};

        // plane d corresponds to shift i = d-4; f2 window index = k + 8 - d
#pragma unroll
        for (int d = 0; d < NP; d++) {
#pragma unroll
            for (int k = 0; k < 4; k++) {
                acc[d][k] = fmaf(av[k], w12[k + 8 - d], acc[d][k]);
            }
        }
    }

    const float inv = 1.0f / (float)FS;
#pragma unroll
    for (int d = 0; d < NP; d++) {
        float4 o = make_float4(acc[d][0] * inv, acc[d][1] * inv,
                               acc[d][2] * inv, acc[d][3] * inv);
        size_t oidx = (((size_t)b * NP + d) * H + h) * W + (size_t)wq * 4;
        *(float4*)(out + oidx) = o;
    }
}

extern "C" void kernel_launch(void* const* d_in, const int* in_sizes, int n_in,
                              void* d_out, int out_size) {
    const float* f1 = (const float*)d_in[0];
    const float* f2 = (const float*)d_in[1];
    float* out = (float*)d_out;

    int total = BS * H * WQ;              // 61440 threads
    int block = 256;
    int grid = (total + block - 1) / block;  // 240 blocks
    cost_volume_kernel<<<grid, block>>>(f1, f2, out);
}

// round 8
// speedup vs baseline: 4.5316x; 4.5316x over previous
#include <cuda_runtime.h>

// CostVolumeBidirectional: f1,f2 (8,96,96,320) f32 -> out (8,9,96,320) f32
// out[b][d][h][w] = (1/96) * sum_c f1[b][c][h][w] * f2[b][c][h][w-(d-4)]
// zero where w-(d-4) outside [0,320).
//
// R5: 4-way channel split per output tile + smem reduction.
// Block = 256 threads = 64 float4-groups x 4 channel-chunks of 24 channels.
// Grid = 61440/64 = 960 blocks -> 245,760 threads (4x the parallelism of R0-4),
// attacking the occupancy/latency bottleneck (occ was 18.8%, DRAM 11.5%).

#define BS 8
#define FS 96
#define H  96
#define W  320
#define WQ (W / 4)      // 80 float4 groups per row
#define NP 9            // disparity planes

#define GROUPS 64       // float4-groups per block
#define CHUNKS 4        // channel chunks per group
#define CHP (FS / CHUNKS)  // 24 channels per thread

__global__ __launch_bounds__(256, 4)
void cost_volume_kernel(const float* __restrict__ f1,
                        const float* __restrict__ f2,
                        float* __restrict__ out) {
    // partial accumulators: [chunk][group][plane] as float4 (4 columns)
    __shared__ float4 s[CHUNKS][GROUPS][NP];   // 36 KB

    const int tid = threadIdx.x;
    const int g   = tid & (GROUPS - 1);
    const int cc  = tid >> 6;

    const int t  = blockIdx.x * GROUPS + g;    // global float4-group id
    const int wq = t % WQ;
    const int bh = t / WQ;
    const int h  = bh % H;
    const int b  = bh / H;

    float acc[NP][4];
#pragma unroll
    for (int d = 0; d < NP; d++)
#pragma unroll
        for (int k = 0; k < 4; k++) acc[d][k] = 0.0f;

    const int cs = H * W;
    const size_t base = ((size_t)b * FS + cc * CHP) * cs + (size_t)h * W + (size_t)wq * 4;
    const float* p1 = f1 + base;
    const float* p2 = f2 + base;

    const bool hasL = (wq > 0);
    const bool hasR = (wq < WQ - 1);
    const float4 z4 = make_float4(0.f, 0.f, 0.f, 0.f);

#pragma unroll 4
    for (int c = 0; c < CHP; c++) {
        const float* q1 = p1 + (size_t)c * cs;
        const float* q2 = p2 + (size_t)c * cs;

        float4 a = *(const float4*)(q1);
        float4 m = *(const float4*)(q2);
        float4 l = hasL ? *(const float4*)(q2 - 4) : z4;
        float4 r = hasR ? *(const float4*)(q2 + 4) : z4;

        float w12[12] = {l.x, l.y, l.z, l.w,
                         m.x, m.y, m.z, m.w,
                         r.x, r.y, r.z, r.w};
        float av[4] = {a.x, a.y, a.z, a.w};

        // plane d => shift i = d-4; f2 window index = k + 8 - d
#pragma unroll
        for (int d = 0; d < NP; d++) {
#pragma unroll
            for (int k = 0; k < 4; k++) {
                acc[d][k] = fmaf(av[k], w12[k + 8 - d], acc[d][k]);
            }
        }
    }

    // stash partials (stride per g is 144B: conflict-free for STS.128 phases)
#pragma unroll
    for (int d = 0; d < NP; d++) {
        s[cc][g][d] = make_float4(acc[d][0], acc[d][1], acc[d][2], acc[d][3]);
    }
    __syncthreads();

    // reduce 4 chunks + write out: 64 groups x 9 planes = 576 float4 stores
    const float inv = 1.0f / (float)FS;
    for (int item = tid; item < GROUPS * NP; item += 256) {
        const int g2 = item / NP;
        const int d  = item % NP;

        float4 a0 = s[0][g2][d];
        float4 a1 = s[1][g2][d];
        float4 a2 = s[2][g2][d];
        float4 a3 = s[3][g2][d];

        float4 o;
        o.x = (a0.x + a1.x + a2.x + a3.x) * inv;
        o.y = (a0.y + a1.y + a2.y + a3.y) * inv;
        o.z = (a0.z + a1.z + a2.z + a3.z) * inv;
        o.w = (a0.w + a1.w + a2.w + a3.w) * inv;

        const int t2  = blockIdx.x * GROUPS + g2;
        const int wq2 = t2 % WQ;
        const int bh2 = t2 / WQ;
        const int h2  = bh2 % H;
        const int b2  = bh2 / H;

        const size_t oidx = (((size_t)b2 * NP + d) * H + h2) * W + (size_t)wq2 * 4;
        *(float4*)(out + oidx) = o;
    }
}

extern "C" void kernel_launch(void* const* d_in, const int* in_sizes, int n_in,
                              void* d_out, int out_size) {
    const float* f1 = (const float*)d_in[0];
    const float* f2 = (const float*)d_in[1];
    float* out = (float*)d_out;

    const int total_groups = BS * H * WQ;          // 61440
    const int grid = total_groups / GROUPS;        // 960 blocks
    cost_volume_kernel<<<grid, 256>>>(f1, f2, out);
}